// round 1
// baseline (speedup 1.0000x reference)
#include <cuda_runtime.h>
#include <math.h>

// ---------------------------------------------------------------------------
// NAM-LSS V2 fused kernel, fp32 scalar baseline.
//
// Structure: grid = 512 CTAs x 256 threads. Each CTA processes TM=32 batch
// rows and loops over all F=64 features. Per-feature weights (W1 32KB,
// W2 64KB, Wr 32KB) staged in shared memory; agg[row][128] lives in
// registers (8 threads per row, 16 columns each). LayerNorm reductions via
// shfl over the 8 lanes of a row. Mixture-beta head computed in-register,
// one output per row. No HBM intermediates, no atomics.
// ---------------------------------------------------------------------------

namespace {
constexpr int B_TOT  = 16384;
constexpr int F      = 64;
constexpr int NB     = 64;
constexpr int H1     = 128;
constexpr int H2     = 128;
constexpr int TM     = 32;     // batch rows per CTA
constexpr int NTHR   = 256;    // 32 rows x 8 column-groups
constexpr float LN_EPS = 1e-5f;

// shared memory layout (in floats)
constexpr int OFF_W1  = 0;                    // [NB][H1]  8192
constexpr int OFF_W2  = OFF_W1 + NB * H1;     // [H1][H2] 16384
constexpr int OFF_WR  = OFF_W2 + H1 * H2;     // [NB][H2]  8192
constexpr int OFF_VEC = OFF_WR + NB * H2;     // b1,g1,be1,b2,g2,be2,br : 7*128
constexpr int OFF_WSM = OFF_VEC + 7 * 128;    // softmax(att) : 64
constexpr int OFF_CEN = OFF_WSM + 64;         // centers[f] : 64
constexpr int OFF_IW  = OFF_CEN + 64;         // 1/width[f] : 64
constexpr int OFF_RBF = OFF_IW + 64;          // [TM][NB+1] pad vs bank conflicts
constexpr int OFF_H   = OFF_RBF + TM * (NB + 1); // [TM][H1+4] pad
constexpr int SMEM_FLOATS = OFF_H + TM * (H1 + 4);
constexpr int SMEM_BYTES  = SMEM_FLOATS * 4;  // 160,640 B
}

__device__ __forceinline__ float red8(float v) {
    // sum over the 8 lanes of one row (lanes (row%4)*8 + cg, cg in [0,8))
    v += __shfl_xor_sync(0xffffffffu, v, 1);
    v += __shfl_xor_sync(0xffffffffu, v, 2);
    v += __shfl_xor_sync(0xffffffffu, v, 4);
    return v;
}

__device__ __forceinline__ float gelu_exact(float v) {
    return 0.5f * v * (1.0f + erff(v * 0.70710678118654752f));
}

__device__ __forceinline__ float softplus_f(float v) {
    return (v > 20.0f) ? v : log1pf(expf(v));
}

__device__ __forceinline__ float clipf(float v, float lo, float hi) {
    return fminf(fmaxf(v, lo), hi);
}

__global__ void __launch_bounds__(NTHR, 1)
nam_kernel(const float* __restrict__ x,        // [B,F]
           const float* __restrict__ centers,  // [F,NB]
           const float* __restrict__ logw,     // [F,NB]
           const float* __restrict__ W1,       // [F,NB,H1]
           const float* __restrict__ b1,       // [F,H1]
           const float* __restrict__ g1,
           const float* __restrict__ be1,
           const float* __restrict__ W2,       // [F,H1,H2]
           const float* __restrict__ b2,
           const float* __restrict__ g2,
           const float* __restrict__ be2,
           const float* __restrict__ Wr,       // [F,NB,H2]
           const float* __restrict__ br,
           const float* __restrict__ att,      // [F]
           const float* __restrict__ bias,     // [H2]
           const float* __restrict__ Wpi,      // [H2,3]
           const float* __restrict__ bpi,      // [3]
           const float* __restrict__ Wa,
           const float* __restrict__ ba,
           const float* __restrict__ Wb,
           const float* __restrict__ bb,
           float* __restrict__ out)            // [B]
{
    extern __shared__ float smem[];
    float* W1s  = smem + OFF_W1;
    float* W2s  = smem + OFF_W2;
    float* Wrs  = smem + OFF_WR;
    float* vecs = smem + OFF_VEC;   // [b1|g1|be1|b2|g2|be2|br] each 128
    float* w_s  = smem + OFF_WSM;
    float* cen_s = smem + OFF_CEN;
    float* iw_s  = smem + OFF_IW;
    float* rbf_s = smem + OFF_RBF;  // [TM][65]
    float* hbuf  = smem + OFF_H;    // [TM][132]

    const int tid  = threadIdx.x;
    const int row  = tid >> 3;        // 0..31
    const int cg   = tid & 7;         // 0..7
    const int col0 = cg * 16;
    const int g_row = blockIdx.x * TM + row;

    // softmax over att -> w_s (cheap, once per CTA)
    if (tid < F) {
        float m = -1e30f;
        for (int i = 0; i < F; ++i) m = fmaxf(m, att[i]);
        float s = 0.0f;
        for (int i = 0; i < F; ++i) s += expf(att[i] - m);
        w_s[tid] = expf(att[tid] - m) / s;
    }

    float agg[16];
#pragma unroll
    for (int j = 0; j < 16; ++j) agg[j] = 0.0f;

    for (int f = 0; f < F; ++f) {
        __syncthreads();  // previous-iteration smem consumers done

        // ---- stage weights for feature f ----
        {
            const float4* s1 = (const float4*)(W1 + (size_t)f * NB * H1);
            const float4* s2 = (const float4*)(W2 + (size_t)f * H1 * H2);
            const float4* sr = (const float4*)(Wr + (size_t)f * NB * H2);
            float4* d1 = (float4*)W1s;
            float4* d2 = (float4*)W2s;
            float4* dr = (float4*)Wrs;
#pragma unroll
            for (int i = 0; i < (NB * H1) / 4 / NTHR; ++i)
                d1[tid + i * NTHR] = s1[tid + i * NTHR];
#pragma unroll
            for (int i = 0; i < (H1 * H2) / 4 / NTHR; ++i)
                d2[tid + i * NTHR] = s2[tid + i * NTHR];
#pragma unroll
            for (int i = 0; i < (NB * H2) / 4 / NTHR; ++i)
                dr[tid + i * NTHR] = sr[tid + i * NTHR];
        }
        if (tid < 128) {
            vecs[tid]         = b1 [f * H1 + tid];
            vecs[128 + tid]   = g1 [f * H1 + tid];
            vecs[256 + tid]   = be1[f * H1 + tid];
            vecs[384 + tid]   = b2 [f * H2 + tid];
            vecs[512 + tid]   = g2 [f * H2 + tid];
            vecs[640 + tid]   = be2[f * H2 + tid];
            vecs[768 + tid]   = br [f * H2 + tid];
        }
        if (tid < NB) {
            cen_s[tid] = centers[f * NB + tid];
            float lw = clipf(logw[f * NB + tid], -5.0f, 5.0f);
            iw_s[tid] = 1.0f / (expf(lw) + 0.1f);
        }
        __syncthreads();

        // ---- RBF expansion for my row (8 basis values per thread) ----
        {
            float xv = clipf(x[(size_t)g_row * F + f], -10.0f, 10.0f);
#pragma unroll
            for (int k = 0; k < 8; ++k) {
                int n = cg * 8 + k;
                float d = (xv - cen_s[n]) * iw_s[n];
                d = clipf(d, -10.0f, 10.0f);
                rbf_s[row * (NB + 1) + n] = __expf(-0.5f * d * d);
            }
        }
        __syncthreads();

        // ---- GEMV1: rbf[64] @ W1[64,128] ----
        float acc[16];
#pragma unroll
        for (int j = 0; j < 16; ++j) acc[j] = 0.0f;
#pragma unroll 4
        for (int n = 0; n < NB; ++n) {
            float r = rbf_s[row * (NB + 1) + n];
            const float4* wp = (const float4*)(W1s + n * H1 + col0);
#pragma unroll
            for (int q = 0; q < 4; ++q) {
                float4 w4 = wp[q];
                acc[q * 4 + 0] = fmaf(r, w4.x, acc[q * 4 + 0]);
                acc[q * 4 + 1] = fmaf(r, w4.y, acc[q * 4 + 1]);
                acc[q * 4 + 2] = fmaf(r, w4.z, acc[q * 4 + 2]);
                acc[q * 4 + 3] = fmaf(r, w4.w, acc[q * 4 + 3]);
            }
        }
        // +b1, LayerNorm, gelu -> hbuf
        {
            float s1 = 0.0f, s2 = 0.0f;
#pragma unroll
            for (int j = 0; j < 16; ++j) {
                float v = acc[j] + vecs[col0 + j];
                acc[j] = v;
                s1 += v;
                s2 += v * v;
            }
            s1 = red8(s1);
            s2 = red8(s2);
            float mu  = s1 * (1.0f / H1);
            float var = s2 * (1.0f / H1) - mu * mu;
            float inv = rsqrtf(var + LN_EPS);
#pragma unroll
            for (int j = 0; j < 16; ++j) {
                float v = (acc[j] - mu) * inv * vecs[128 + col0 + j] + vecs[256 + col0 + j];
                hbuf[row * (H1 + 4) + col0 + j] = gelu_exact(v);
            }
        }
        __syncthreads();

        // ---- GEMV2: h[128] @ W2[128,128] ----
#pragma unroll
        for (int j = 0; j < 16; ++j) acc[j] = 0.0f;
#pragma unroll 4
        for (int i = 0; i < H1; ++i) {
            float hv = hbuf[row * (H1 + 4) + i];
            const float4* wp = (const float4*)(W2s + i * H2 + col0);
#pragma unroll
            for (int q = 0; q < 4; ++q) {
                float4 w4 = wp[q];
                acc[q * 4 + 0] = fmaf(hv, w4.x, acc[q * 4 + 0]);
                acc[q * 4 + 1] = fmaf(hv, w4.y, acc[q * 4 + 1]);
                acc[q * 4 + 2] = fmaf(hv, w4.z, acc[q * 4 + 2]);
                acc[q * 4 + 3] = fmaf(hv, w4.w, acc[q * 4 + 3]);
            }
        }
        // +b2, LayerNorm, gelu (keep in acc)
        {
            float s1 = 0.0f, s2 = 0.0f;
#pragma unroll
            for (int j = 0; j < 16; ++j) {
                float v = acc[j] + vecs[384 + col0 + j];
                acc[j] = v;
                s1 += v;
                s2 += v * v;
            }
            s1 = red8(s1);
            s2 = red8(s2);
            float mu  = s1 * (1.0f / H2);
            float var = s2 * (1.0f / H2) - mu * mu;
            float inv = rsqrtf(var + LN_EPS);
#pragma unroll
            for (int j = 0; j < 16; ++j) {
                float v = (acc[j] - mu) * inv * vecs[512 + col0 + j] + vecs[640 + col0 + j];
                acc[j] = gelu_exact(v);
            }
        }

        // ---- residual GEMV: rbf[64] @ Wr[64,128] ----
        float accr[16];
#pragma unroll
        for (int j = 0; j < 16; ++j) accr[j] = 0.0f;
#pragma unroll 4
        for (int n = 0; n < NB; ++n) {
            float r = rbf_s[row * (NB + 1) + n];
            const float4* wp = (const float4*)(Wrs + n * H2 + col0);
#pragma unroll
            for (int q = 0; q < 4; ++q) {
                float4 w4 = wp[q];
                accr[q * 4 + 0] = fmaf(r, w4.x, accr[q * 4 + 0]);
                accr[q * 4 + 1] = fmaf(r, w4.y, accr[q * 4 + 1]);
                accr[q * 4 + 2] = fmaf(r, w4.z, accr[q * 4 + 2]);
                accr[q * 4 + 3] = fmaf(r, w4.w, accr[q * 4 + 3]);
            }
        }

        // ---- stacked = h + 0.1*(res + br); agg += w[f]*stacked ----
        {
            float wf = w_s[f];
#pragma unroll
            for (int j = 0; j < 16; ++j) {
                float st = acc[j] + 0.1f * (accr[j] + vecs[768 + col0 + j]);
                agg[j] = fmaf(wf, st, agg[j]);
            }
        }
    }

    // ---- head: agg += bias; pi/alpha/beta mixture ----
#pragma unroll
    for (int j = 0; j < 16; ++j) agg[j] += bias[col0 + j];

    float ppi[3] = {0.f, 0.f, 0.f};
    float pa [3] = {0.f, 0.f, 0.f};
    float pb [3] = {0.f, 0.f, 0.f};
#pragma unroll
    for (int j = 0; j < 16; ++j) {
        float a = agg[j];
        int r = col0 + j;
#pragma unroll
        for (int k = 0; k < 3; ++k) {
            ppi[k] = fmaf(a, Wpi[r * 3 + k], ppi[k]);
            pa [k] = fmaf(a, Wa [r * 3 + k], pa [k]);
            pb [k] = fmaf(a, Wb [r * 3 + k], pb [k]);
        }
    }
#pragma unroll
    for (int k = 0; k < 3; ++k) {
        ppi[k] = red8(ppi[k]);
        pa [k] = red8(pa [k]);
        pb [k] = red8(pb [k]);
    }

    if (cg == 0) {
        float l[3], e[3];
        float m = -1e30f;
#pragma unroll
        for (int k = 0; k < 3; ++k) {
            l[k] = ppi[k] + bpi[k];
            m = fmaxf(m, l[k]);
        }
        float es = 0.0f;
#pragma unroll
        for (int k = 0; k < 3; ++k) {
            e[k] = expf(l[k] - m);
            es += e[k];
        }
        float inv_es = 1.0f / es;
        float pred = 0.0f;
#pragma unroll
        for (int k = 0; k < 3; ++k) {
            float ak = clipf(softplus_f(pa[k] + ba[k]) + 1.01f, 1.01f, 100.0f);
            float bk = clipf(softplus_f(pb[k] + bb[k]) + 1.01f, 1.01f, 100.0f);
            pred += (e[k] * inv_es) * (ak / (ak + bk));
        }
        out[g_row] = clipf(pred, 0.001f, 0.999f);
    }
}

extern "C" void kernel_launch(void* const* d_in, const int* in_sizes, int n_in,
                              void* d_out, int out_size) {
    (void)in_sizes; (void)n_in; (void)out_size;
    cudaFuncSetAttribute(nam_kernel,
                         cudaFuncAttributeMaxDynamicSharedMemorySize, SMEM_BYTES);
    const float* x       = (const float*)d_in[0];
    const float* centers = (const float*)d_in[1];
    const float* logw    = (const float*)d_in[2];
    const float* W1      = (const float*)d_in[3];
    const float* b1      = (const float*)d_in[4];
    const float* g1      = (const float*)d_in[5];
    const float* be1     = (const float*)d_in[6];
    const float* W2      = (const float*)d_in[7];
    const float* b2      = (const float*)d_in[8];
    const float* g2      = (const float*)d_in[9];
    const float* be2     = (const float*)d_in[10];
    const float* Wr      = (const float*)d_in[11];
    const float* br      = (const float*)d_in[12];
    const float* att     = (const float*)d_in[13];
    const float* bias    = (const float*)d_in[14];
    const float* Wpi     = (const float*)d_in[15];
    const float* bpi     = (const float*)d_in[16];
    const float* Wa      = (const float*)d_in[17];
    const float* ba      = (const float*)d_in[18];
    const float* Wb      = (const float*)d_in[19];
    const float* bb      = (const float*)d_in[20];
    float* out = (float*)d_out;

    nam_kernel<<<B_TOT / TM, NTHR, SMEM_BYTES>>>(
        x, centers, logw, W1, b1, g1, be1, W2, b2, g2, be2, Wr, br,
        att, bias, Wpi, bpi, Wa, ba, Wb, bb, out);
}

// round 4
// speedup vs baseline: 7.8103x; 7.8103x over previous
#include <cuda_runtime.h>
#include <math.h>

// ---------------------------------------------------------------------------
// NAM-LSS V2 fused kernel, v2b: register-blocked rows (R=4), 512 thr/CTA,
// with rbf/h tiles ALIASED into one scratch region (smem 186KB -> 169KB)
// as a hedge against the two container failures seen with the 186KB build.
//
// Grid = 256 CTAs x 512 threads. Each CTA owns TM=64 batch rows, loops over
// F=64 features with weights staged in smem. Warp rg (0..15) owns rows
// {rg, rg+16, rg+32, rg+48}; lane cg owns cols cg*4..+3. One weight float4
// feeds 4 rows (16 FMAs). rbf scratch is consumed by GEMV1+residual, then a
// CTA barrier, then the same region is reused for the h tile (stride 132).
// ---------------------------------------------------------------------------

namespace {
constexpr int B_TOT  = 16384;
constexpr int F      = 64;
constexpr int NB     = 64;
constexpr int H1     = 128;
constexpr int H2     = 128;
constexpr int TM     = 64;     // batch rows per CTA
constexpr int R      = 4;      // rows per thread
constexpr int NTHR   = 512;    // 16 warps
constexpr float LN_EPS = 1e-5f;

constexpr int S_RBF = NB + 2;   // 66 (float2-aligned)
constexpr int S_H   = H1 + 4;   // 132 (float4-aligned)

// shared memory layout (floats)
constexpr int OFF_W1   = 0;                      // [NB][H1]  8192
constexpr int OFF_W2   = OFF_W1 + NB * H1;       // [H1][H2] 16384
constexpr int OFF_WR   = OFF_W2 + H1 * H2;       // [NB][H2]  8192
constexpr int OFF_VEC  = OFF_WR + NB * H2;       // b1,g1,be1,b2,g2,be2,br
constexpr int OFF_WSM  = OFF_VEC + 7 * 128;      // softmax(att)
constexpr int OFF_CEN  = OFF_WSM + 64;
constexpr int OFF_IW   = OFF_CEN + 64;
constexpr int OFF_SCR  = OFF_IW + 64;            // rbf [TM][66] / h [TM][132]
constexpr int SMEM_FLOATS = OFF_SCR + TM * S_H;
constexpr int SMEM_BYTES  = SMEM_FLOATS * 4;     // 169,216 B
}

__device__ __forceinline__ float red32(float v) {
    v += __shfl_xor_sync(0xffffffffu, v, 1);
    v += __shfl_xor_sync(0xffffffffu, v, 2);
    v += __shfl_xor_sync(0xffffffffu, v, 4);
    v += __shfl_xor_sync(0xffffffffu, v, 8);
    v += __shfl_xor_sync(0xffffffffu, v, 16);
    return v;
}

__device__ __forceinline__ float gelu_exact(float v) {
    return 0.5f * v * (1.0f + erff(v * 0.70710678118654752f));
}

__device__ __forceinline__ float softplus_f(float v) {
    return (v > 20.0f) ? v : log1pf(expf(v));
}

__device__ __forceinline__ float clipf(float v, float lo, float hi) {
    return fminf(fmaxf(v, lo), hi);
}

__global__ void __launch_bounds__(NTHR, 1)
nam_kernel(const float* __restrict__ x,        // [B,F]
           const float* __restrict__ centers,  // [F,NB]
           const float* __restrict__ logw,     // [F,NB]
           const float* __restrict__ W1,       // [F,NB,H1]
           const float* __restrict__ b1,
           const float* __restrict__ g1,
           const float* __restrict__ be1,
           const float* __restrict__ W2,       // [F,H1,H2]
           const float* __restrict__ b2,
           const float* __restrict__ g2,
           const float* __restrict__ be2,
           const float* __restrict__ Wr,       // [F,NB,H2]
           const float* __restrict__ br,
           const float* __restrict__ att,      // [F]
           const float* __restrict__ bias,     // [H2]
           const float* __restrict__ Wpi,      // [H2,3]
           const float* __restrict__ bpi,
           const float* __restrict__ Wa,
           const float* __restrict__ ba,
           const float* __restrict__ Wb,
           const float* __restrict__ bb,
           float* __restrict__ out)            // [B]
{
    extern __shared__ float smem[];
    float* W1s   = smem + OFF_W1;
    float* W2s   = smem + OFF_W2;
    float* Wrs   = smem + OFF_WR;
    float* vecs  = smem + OFF_VEC;
    float* w_s   = smem + OFF_WSM;
    float* cen_s = smem + OFF_CEN;
    float* iw_s  = smem + OFF_IW;
    float* rbf_s = smem + OFF_SCR;   // [TM][S_RBF]  (phase 1)
    float* hbuf  = smem + OFF_SCR;   // [TM][S_H]    (phase 2, aliased)

    const int tid  = threadIdx.x;
    const int cg   = tid & 31;        // lane: 4 cols
    const int rg   = tid >> 5;        // warp: rows {rg+16k}
    const int col0 = cg * 4;
    const int base_row = blockIdx.x * TM;

    // softmax over att (once per CTA; visible after first __syncthreads)
    if (tid < F) {
        float m = -1e30f;
        for (int i = 0; i < F; ++i) m = fmaxf(m, att[i]);
        float s = 0.0f;
        for (int i = 0; i < F; ++i) s += expf(att[i] - m);
        w_s[tid] = expf(att[tid] - m) / s;
    }

    float agg[16];
#pragma unroll
    for (int j = 0; j < 16; ++j) agg[j] = 0.0f;

    for (int f = 0; f < F; ++f) {
        __syncthreads();   // prev feature's hbuf reads done; smem reusable

        // ---- stage weights (LDG -> STS, 16 float4/thread) ----
        {
            const float4* s1 = (const float4*)(W1 + (size_t)f * NB * H1);
            const float4* s2 = (const float4*)(W2 + (size_t)f * H1 * H2);
            const float4* sr = (const float4*)(Wr + (size_t)f * NB * H2);
            float4* d1 = (float4*)W1s;
            float4* d2 = (float4*)W2s;
            float4* dr = (float4*)Wrs;
#pragma unroll
            for (int i = 0; i < (NB * H1) / 4 / NTHR; ++i)
                d1[tid + i * NTHR] = s1[tid + i * NTHR];
#pragma unroll
            for (int i = 0; i < (H1 * H2) / 4 / NTHR; ++i)
                d2[tid + i * NTHR] = s2[tid + i * NTHR];
#pragma unroll
            for (int i = 0; i < (NB * H2) / 4 / NTHR; ++i)
                dr[tid + i * NTHR] = sr[tid + i * NTHR];
        }
        if (tid < 128) {
            vecs[tid]         = b1 [f * H1 + tid];
            vecs[128 + tid]   = g1 [f * H1 + tid];
            vecs[256 + tid]   = be1[f * H1 + tid];
            vecs[384 + tid]   = b2 [f * H2 + tid];
            vecs[512 + tid]   = g2 [f * H2 + tid];
            vecs[640 + tid]   = be2[f * H2 + tid];
            vecs[768 + tid]   = br [f * H2 + tid];
        } else if (tid >= 256 && tid < 320) {
            int t = tid - 256;
            cen_s[t] = centers[f * NB + t];
            float lw = clipf(logw[f * NB + t], -5.0f, 5.0f);
            iw_s[t] = 1.0f / (expf(lw) + 0.1f);
        }
        __syncthreads();

        // ---- RBF: warp computes its 4 rows; lane does n = 2cg, 2cg+1 ----
        {
            int n0 = cg * 2;
            float c0 = cen_s[n0],  c1 = cen_s[n0 + 1];
            float i0 = iw_s[n0],   i1 = iw_s[n0 + 1];
#pragma unroll
            for (int k = 0; k < R; ++k) {
                int row = rg + 16 * k;
                float xv = clipf(__ldg(x + (size_t)(base_row + row) * F + f), -10.0f, 10.0f);
                float d0 = clipf((xv - c0) * i0, -10.0f, 10.0f);
                float d1v = clipf((xv - c1) * i1, -10.0f, 10.0f);
                float2 e;
                e.x = __expf(-0.5f * d0 * d0);
                e.y = __expf(-0.5f * d1v * d1v);
                *(float2*)(rbf_s + row * S_RBF + n0) = e;
            }
        }
        __syncwarp();

        // ---- GEMV1 + residual GEMV fused: rbf[64] @ (W1|Wr)[64,128] ----
        float acc[16], accr[16];
#pragma unroll
        for (int j = 0; j < 16; ++j) { acc[j] = 0.0f; accr[j] = 0.0f; }
#pragma unroll 2
        for (int n2 = 0; n2 < NB / 2; ++n2) {
            float2 rb[R];
#pragma unroll
            for (int k = 0; k < R; ++k)
                rb[k] = *(const float2*)(rbf_s + (rg + 16 * k) * S_RBF + n2 * 2);
#pragma unroll
            for (int t = 0; t < 2; ++t) {
                int n = n2 * 2 + t;
                float4 w1 = *(const float4*)(W1s + n * H1 + col0);
                float4 wr = *(const float4*)(Wrs + n * H2 + col0);
#pragma unroll
                for (int k = 0; k < R; ++k) {
                    float r = t ? rb[k].y : rb[k].x;
                    acc [k*4+0] = fmaf(r, w1.x, acc [k*4+0]);
                    acc [k*4+1] = fmaf(r, w1.y, acc [k*4+1]);
                    acc [k*4+2] = fmaf(r, w1.z, acc [k*4+2]);
                    acc [k*4+3] = fmaf(r, w1.w, acc [k*4+3]);
                    accr[k*4+0] = fmaf(r, wr.x, accr[k*4+0]);
                    accr[k*4+1] = fmaf(r, wr.y, accr[k*4+1]);
                    accr[k*4+2] = fmaf(r, wr.z, accr[k*4+2]);
                    accr[k*4+3] = fmaf(r, wr.w, accr[k*4+3]);
                }
            }
        }

        // All rbf reads (every warp) must finish before hbuf overwrites the
        // aliased scratch region.
        __syncthreads();

        // ---- +b1, LN, gelu -> hbuf (aliased scratch, stride S_H) ----
#pragma unroll
        for (int k = 0; k < R; ++k) {
            float s1 = 0.0f, s2 = 0.0f;
#pragma unroll
            for (int j = 0; j < 4; ++j) {
                float v = acc[k*4+j] + vecs[col0 + j];
                acc[k*4+j] = v;
                s1 += v; s2 += v * v;
            }
            s1 = red32(s1); s2 = red32(s2);
            float mu  = s1 * (1.0f / H1);
            float var = s2 * (1.0f / H1) - mu * mu;
            float inv = rsqrtf(var + LN_EPS);
            float4 hv;
            hv.x = gelu_exact((acc[k*4+0] - mu) * inv * vecs[128 + col0 + 0] + vecs[256 + col0 + 0]);
            hv.y = gelu_exact((acc[k*4+1] - mu) * inv * vecs[128 + col0 + 1] + vecs[256 + col0 + 1]);
            hv.z = gelu_exact((acc[k*4+2] - mu) * inv * vecs[128 + col0 + 2] + vecs[256 + col0 + 2]);
            hv.w = gelu_exact((acc[k*4+3] - mu) * inv * vecs[128 + col0 + 3] + vecs[256 + col0 + 3]);
            *(float4*)(hbuf + (rg + 16 * k) * S_H + col0) = hv;
        }
        __syncwarp();   // h rows are warp-private from here

        // ---- GEMV2: h[128] @ W2[128,128] ----
#pragma unroll
        for (int j = 0; j < 16; ++j) acc[j] = 0.0f;
#pragma unroll 2
        for (int i4 = 0; i4 < H1 / 4; ++i4) {
            float4 hv[R];
#pragma unroll
            for (int k = 0; k < R; ++k)
                hv[k] = *(const float4*)(hbuf + (rg + 16 * k) * S_H + i4 * 4);
#pragma unroll
            for (int t = 0; t < 4; ++t) {
                int i = i4 * 4 + t;
                float4 w2 = *(const float4*)(W2s + i * H2 + col0);
#pragma unroll
                for (int k = 0; k < R; ++k) {
                    float h = (t == 0) ? hv[k].x : (t == 1) ? hv[k].y : (t == 2) ? hv[k].z : hv[k].w;
                    acc[k*4+0] = fmaf(h, w2.x, acc[k*4+0]);
                    acc[k*4+1] = fmaf(h, w2.y, acc[k*4+1]);
                    acc[k*4+2] = fmaf(h, w2.z, acc[k*4+2]);
                    acc[k*4+3] = fmaf(h, w2.w, acc[k*4+3]);
                }
            }
        }

        // ---- +b2, LN, gelu; stacked; agg += w[f]*stacked ----
        {
            float wf = w_s[f];
#pragma unroll
            for (int k = 0; k < R; ++k) {
                float s1 = 0.0f, s2 = 0.0f;
#pragma unroll
                for (int j = 0; j < 4; ++j) {
                    float v = acc[k*4+j] + vecs[384 + col0 + j];
                    acc[k*4+j] = v;
                    s1 += v; s2 += v * v;
                }
                s1 = red32(s1); s2 = red32(s2);
                float mu  = s1 * (1.0f / H2);
                float var = s2 * (1.0f / H2) - mu * mu;
                float inv = rsqrtf(var + LN_EPS);
#pragma unroll
                for (int j = 0; j < 4; ++j) {
                    float hv = gelu_exact((acc[k*4+j] - mu) * inv * vecs[512 + col0 + j] + vecs[640 + col0 + j]);
                    float st = hv + 0.1f * (accr[k*4+j] + vecs[768 + col0 + j]);
                    agg[k*4+j] = fmaf(wf, st, agg[k*4+j]);
                }
            }
        }
    }

    // ---- head: per-row dots with Wpi/Wa/Wb, reduce over warp ----
    float ppi[12], paa[12], pbb[12];
#pragma unroll
    for (int q = 0; q < 12; ++q) { ppi[q] = 0.f; paa[q] = 0.f; pbb[q] = 0.f; }

#pragma unroll
    for (int j = 0; j < 4; ++j) {
        int r = col0 + j;
        float wp0 = __ldg(Wpi + r * 3 + 0), wp1 = __ldg(Wpi + r * 3 + 1), wp2 = __ldg(Wpi + r * 3 + 2);
        float wa0 = __ldg(Wa  + r * 3 + 0), wa1 = __ldg(Wa  + r * 3 + 1), wa2 = __ldg(Wa  + r * 3 + 2);
        float wb0 = __ldg(Wb  + r * 3 + 0), wb1 = __ldg(Wb  + r * 3 + 1), wb2 = __ldg(Wb  + r * 3 + 2);
        float bs = __ldg(bias + r);
#pragma unroll
        for (int k = 0; k < R; ++k) {
            float a = agg[k*4+j] + bs;
            ppi[k*3+0] = fmaf(a, wp0, ppi[k*3+0]);
            ppi[k*3+1] = fmaf(a, wp1, ppi[k*3+1]);
            ppi[k*3+2] = fmaf(a, wp2, ppi[k*3+2]);
            paa[k*3+0] = fmaf(a, wa0, paa[k*3+0]);
            paa[k*3+1] = fmaf(a, wa1, paa[k*3+1]);
            paa[k*3+2] = fmaf(a, wa2, paa[k*3+2]);
            pbb[k*3+0] = fmaf(a, wb0, pbb[k*3+0]);
            pbb[k*3+1] = fmaf(a, wb1, pbb[k*3+1]);
            pbb[k*3+2] = fmaf(a, wb2, pbb[k*3+2]);
        }
    }
#pragma unroll
    for (int q = 0; q < 12; ++q) {
        ppi[q] = red32(ppi[q]);
        paa[q] = red32(paa[q]);
        pbb[q] = red32(pbb[q]);
    }

    if (cg < R) {
        int k = cg;                 // lane k writes row rg+16k
        float l0 = ppi[k*3+0] + __ldg(bpi + 0);
        float l1 = ppi[k*3+1] + __ldg(bpi + 1);
        float l2 = ppi[k*3+2] + __ldg(bpi + 2);
        float m = fmaxf(l0, fmaxf(l1, l2));
        float e0 = expf(l0 - m), e1 = expf(l1 - m), e2 = expf(l2 - m);
        float inv_es = 1.0f / (e0 + e1 + e2);
        float pred = 0.0f;
#pragma unroll
        for (int q = 0; q < 3; ++q) {
            float ev = (q == 0) ? e0 : (q == 1) ? e1 : e2;
            float ak = clipf(softplus_f(paa[k*3+q] + __ldg(ba + q)) + 1.01f, 1.01f, 100.0f);
            float bk = clipf(softplus_f(pbb[k*3+q] + __ldg(bb + q)) + 1.01f, 1.01f, 100.0f);
            pred += (ev * inv_es) * (ak / (ak + bk));
        }
        out[base_row + rg + 16 * k] = clipf(pred, 0.001f, 0.999f);
    }
}

extern "C" void kernel_launch(void* const* d_in, const int* in_sizes, int n_in,
                              void* d_out, int out_size) {
    (void)in_sizes; (void)n_in; (void)out_size;
    cudaFuncSetAttribute(nam_kernel,
                         cudaFuncAttributeMaxDynamicSharedMemorySize, SMEM_BYTES);
    const float* x       = (const float*)d_in[0];
    const float* centers = (const float*)d_in[1];
    const float* logw    = (const float*)d_in[2];
    const float* W1      = (const float*)d_in[3];
    const float* b1      = (const float*)d_in[4];
    const float* g1      = (const float*)d_in[5];
    const float* be1     = (const float*)d_in[6];
    const float* W2      = (const float*)d_in[7];
    const float* b2      = (const float*)d_in[8];
    const float* g2      = (const float*)d_in[9];
    const float* be2     = (const float*)d_in[10];
    const float* Wr      = (const float*)d_in[11];
    const float* br      = (const float*)d_in[12];
    const float* att     = (const float*)d_in[13];
    const float* bias    = (const float*)d_in[14];
    const float* Wpi     = (const float*)d_in[15];
    const float* bpi     = (const float*)d_in[16];
    const float* Wa      = (const float*)d_in[17];
    const float* ba      = (const float*)d_in[18];
    const float* Wb      = (const float*)d_in[19];
    const float* bb      = (const float*)d_in[20];
    float* out = (float*)d_out;

    nam_kernel<<<B_TOT / TM, NTHR, SMEM_BYTES>>>(
        x, centers, logw, W1, b1, g1, be1, W2, b2, g2, be2, Wr, br,
        att, bias, Wpi, bpi, Wa, ba, Wb, bb, out);
}

// round 5
// speedup vs baseline: 8.3880x; 1.0740x over previous
#include <cuda_runtime.h>
#include <math.h>

// ---------------------------------------------------------------------------
// NAM-LSS V2 fused kernel, v3: packed fp32 (fma.rn.f32x2 / FFMA2) inner
// loops. Same structure as v2b (R=4 rows/thread, 512 thr, 169KB smem with
// rbf/h aliased scratch); all GEMV FMAs now operate on f32x2 pairs, halving
// FMA instruction count. Bitwise-identical fp32 arithmetic.
// ---------------------------------------------------------------------------

namespace {
constexpr int B_TOT  = 16384;
constexpr int F      = 64;
constexpr int NB     = 64;
constexpr int H1     = 128;
constexpr int H2     = 128;
constexpr int TM     = 64;     // batch rows per CTA
constexpr int R      = 4;      // rows per thread
constexpr int NTHR   = 512;    // 16 warps
constexpr float LN_EPS = 1e-5f;

constexpr int S_RBF = NB + 2;   // 66
constexpr int S_H   = H1 + 4;   // 132

constexpr int OFF_W1   = 0;                      // [NB][H1]  8192
constexpr int OFF_W2   = OFF_W1 + NB * H1;       // [H1][H2] 16384
constexpr int OFF_WR   = OFF_W2 + H1 * H2;       // [NB][H2]  8192
constexpr int OFF_VEC  = OFF_WR + NB * H2;       // b1,g1,be1,b2,g2,be2,br
constexpr int OFF_WSM  = OFF_VEC + 7 * 128;
constexpr int OFF_CEN  = OFF_WSM + 64;
constexpr int OFF_IW   = OFF_CEN + 64;
constexpr int OFF_SCR  = OFF_IW + 64;            // rbf [TM][66] / h [TM][132]
constexpr int SMEM_FLOATS = OFF_SCR + TM * S_H;
constexpr int SMEM_BYTES  = SMEM_FLOATS * 4;     // 169,216 B
}

typedef unsigned long long u64;

__device__ __forceinline__ void fma2(u64& d, u64 a, u64 b) {
    // d = a * b + d  (two packed fp32 lanes)
    asm("fma.rn.f32x2 %0, %1, %2, %0;" : "+l"(d) : "l"(a), "l"(b));
}

__device__ __forceinline__ u64 pack2(float v) {
    u64 r;
    asm("mov.b64 %0, {%1, %1};" : "=l"(r) : "f"(v));
    return r;
}

__device__ __forceinline__ float2 unpack2(u64 v) {
    float2 f;
    asm("mov.b64 {%0, %1}, %2;" : "=f"(f.x), "=f"(f.y) : "l"(v));
    return f;
}

__device__ __forceinline__ float red32(float v) {
    v += __shfl_xor_sync(0xffffffffu, v, 1);
    v += __shfl_xor_sync(0xffffffffu, v, 2);
    v += __shfl_xor_sync(0xffffffffu, v, 4);
    v += __shfl_xor_sync(0xffffffffu, v, 8);
    v += __shfl_xor_sync(0xffffffffu, v, 16);
    return v;
}

__device__ __forceinline__ float gelu_exact(float v) {
    return 0.5f * v * (1.0f + erff(v * 0.70710678118654752f));
}

__device__ __forceinline__ float softplus_f(float v) {
    return (v > 20.0f) ? v : log1pf(expf(v));
}

__device__ __forceinline__ float clipf(float v, float lo, float hi) {
    return fminf(fmaxf(v, lo), hi);
}

__global__ void __launch_bounds__(NTHR, 1)
nam_kernel(const float* __restrict__ x,        // [B,F]
           const float* __restrict__ centers,  // [F,NB]
           const float* __restrict__ logw,     // [F,NB]
           const float* __restrict__ W1,       // [F,NB,H1]
           const float* __restrict__ b1,
           const float* __restrict__ g1,
           const float* __restrict__ be1,
           const float* __restrict__ W2,       // [F,H1,H2]
           const float* __restrict__ b2,
           const float* __restrict__ g2,
           const float* __restrict__ be2,
           const float* __restrict__ Wr,       // [F,NB,H2]
           const float* __restrict__ br,
           const float* __restrict__ att,      // [F]
           const float* __restrict__ bias,     // [H2]
           const float* __restrict__ Wpi,      // [H2,3]
           const float* __restrict__ bpi,
           const float* __restrict__ Wa,
           const float* __restrict__ ba,
           const float* __restrict__ Wb,
           const float* __restrict__ bb,
           float* __restrict__ out)            // [B]
{
    extern __shared__ float smem[];
    float* W1s   = smem + OFF_W1;
    float* W2s   = smem + OFF_W2;
    float* Wrs   = smem + OFF_WR;
    float* vecs  = smem + OFF_VEC;
    float* w_s   = smem + OFF_WSM;
    float* cen_s = smem + OFF_CEN;
    float* iw_s  = smem + OFF_IW;
    float* rbf_s = smem + OFF_SCR;   // [TM][S_RBF]  (phase 1)
    float* hbuf  = smem + OFF_SCR;   // [TM][S_H]    (phase 2, aliased)

    const int tid  = threadIdx.x;
    const int cg   = tid & 31;        // lane: 4 cols (2 f32x2 pairs)
    const int rg   = tid >> 5;        // warp: rows {rg+16k}
    const int col0 = cg * 4;
    const int base_row = blockIdx.x * TM;

    if (tid < F) {
        float m = -1e30f;
        for (int i = 0; i < F; ++i) m = fmaxf(m, att[i]);
        float s = 0.0f;
        for (int i = 0; i < F; ++i) s += expf(att[i] - m);
        w_s[tid] = expf(att[tid] - m) / s;
    }

    float agg[16];
#pragma unroll
    for (int j = 0; j < 16; ++j) agg[j] = 0.0f;

    for (int f = 0; f < F; ++f) {
        __syncthreads();   // prev feature's smem consumers done

        // ---- stage weights (LDG -> STS, 16 float4/thread) ----
        {
            const float4* s1 = (const float4*)(W1 + (size_t)f * NB * H1);
            const float4* s2 = (const float4*)(W2 + (size_t)f * H1 * H2);
            const float4* sr = (const float4*)(Wr + (size_t)f * NB * H2);
            float4* d1 = (float4*)W1s;
            float4* d2 = (float4*)W2s;
            float4* dr = (float4*)Wrs;
#pragma unroll
            for (int i = 0; i < (NB * H1) / 4 / NTHR; ++i)
                d1[tid + i * NTHR] = s1[tid + i * NTHR];
#pragma unroll
            for (int i = 0; i < (H1 * H2) / 4 / NTHR; ++i)
                d2[tid + i * NTHR] = s2[tid + i * NTHR];
#pragma unroll
            for (int i = 0; i < (NB * H2) / 4 / NTHR; ++i)
                dr[tid + i * NTHR] = sr[tid + i * NTHR];
        }
        if (tid < 128) {
            vecs[tid]         = b1 [f * H1 + tid];
            vecs[128 + tid]   = g1 [f * H1 + tid];
            vecs[256 + tid]   = be1[f * H1 + tid];
            vecs[384 + tid]   = b2 [f * H2 + tid];
            vecs[512 + tid]   = g2 [f * H2 + tid];
            vecs[640 + tid]   = be2[f * H2 + tid];
            vecs[768 + tid]   = br [f * H2 + tid];
        } else if (tid >= 256 && tid < 320) {
            int t = tid - 256;
            cen_s[t] = centers[f * NB + t];
            float lw = clipf(logw[f * NB + t], -5.0f, 5.0f);
            iw_s[t] = 1.0f / (expf(lw) + 0.1f);
        }
        __syncthreads();

        // ---- RBF: warp computes its 4 rows; lane does n = 2cg, 2cg+1 ----
        {
            int n0 = cg * 2;
            float c0 = cen_s[n0],  c1 = cen_s[n0 + 1];
            float i0 = iw_s[n0],   i1 = iw_s[n0 + 1];
#pragma unroll
            for (int k = 0; k < R; ++k) {
                int row = rg + 16 * k;
                float xv = clipf(__ldg(x + (size_t)(base_row + row) * F + f), -10.0f, 10.0f);
                float d0 = clipf((xv - c0) * i0, -10.0f, 10.0f);
                float d1v = clipf((xv - c1) * i1, -10.0f, 10.0f);
                float2 e;
                e.x = __expf(-0.5f * d0 * d0);
                e.y = __expf(-0.5f * d1v * d1v);
                *(float2*)(rbf_s + row * S_RBF + n0) = e;
            }
        }
        __syncwarp();

        // ---- GEMV1 + residual fused (packed f32x2):
        //      acc2[k][p], accr2[k][p], p=0,1 covers cols col0+2p..+2p+1 ----
        u64 acc2[8], accr2[8];
#pragma unroll
        for (int j = 0; j < 8; ++j) { acc2[j] = 0ull; accr2[j] = 0ull; }
#pragma unroll 2
        for (int n2 = 0; n2 < NB / 2; ++n2) {
            float2 rb[R];
#pragma unroll
            for (int k = 0; k < R; ++k)
                rb[k] = *(const float2*)(rbf_s + (rg + 16 * k) * S_RBF + n2 * 2);
#pragma unroll
            for (int t = 0; t < 2; ++t) {
                int n = n2 * 2 + t;
                ulonglong2 w1p = *(const ulonglong2*)(W1s + n * H1 + col0);
                ulonglong2 wrp = *(const ulonglong2*)(Wrs + n * H2 + col0);
#pragma unroll
                for (int k = 0; k < R; ++k) {
                    u64 rr = pack2(t ? rb[k].y : rb[k].x);
                    fma2(acc2 [k*2+0], rr, w1p.x);
                    fma2(acc2 [k*2+1], rr, w1p.y);
                    fma2(accr2[k*2+0], rr, wrp.x);
                    fma2(accr2[k*2+1], rr, wrp.y);
                }
            }
        }

        // all rbf reads done before hbuf overwrites aliased scratch
        __syncthreads();

        // ---- +b1, LN, gelu -> hbuf ----
#pragma unroll
        for (int k = 0; k < R; ++k) {
            float2 p0 = unpack2(acc2[k*2+0]);
            float2 p1 = unpack2(acc2[k*2+1]);
            float v0 = p0.x + vecs[col0 + 0];
            float v1 = p0.y + vecs[col0 + 1];
            float v2 = p1.x + vecs[col0 + 2];
            float v3 = p1.y + vecs[col0 + 3];
            float s1 = red32(v0 + v1 + v2 + v3);
            float s2 = red32(v0*v0 + v1*v1 + v2*v2 + v3*v3);
            float mu  = s1 * (1.0f / H1);
            float var = s2 * (1.0f / H1) - mu * mu;
            float inv = rsqrtf(var + LN_EPS);
            float4 hv;
            hv.x = gelu_exact((v0 - mu) * inv * vecs[128 + col0 + 0] + vecs[256 + col0 + 0]);
            hv.y = gelu_exact((v1 - mu) * inv * vecs[128 + col0 + 1] + vecs[256 + col0 + 1]);
            hv.z = gelu_exact((v2 - mu) * inv * vecs[128 + col0 + 2] + vecs[256 + col0 + 2]);
            hv.w = gelu_exact((v3 - mu) * inv * vecs[128 + col0 + 3] + vecs[256 + col0 + 3]);
            *(float4*)(hbuf + (rg + 16 * k) * S_H + col0) = hv;
        }
        __syncwarp();   // h rows warp-private from here

        // ---- GEMV2 (packed): h[128] @ W2[128,128] ----
        u64 accb[8];
#pragma unroll
        for (int j = 0; j < 8; ++j) accb[j] = 0ull;
#pragma unroll 2
        for (int i4 = 0; i4 < H1 / 4; ++i4) {
            float4 hv[R];
#pragma unroll
            for (int k = 0; k < R; ++k)
                hv[k] = *(const float4*)(hbuf + (rg + 16 * k) * S_H + i4 * 4);
#pragma unroll
            for (int t = 0; t < 4; ++t) {
                int i = i4 * 4 + t;
                ulonglong2 w2p = *(const ulonglong2*)(W2s + i * H2 + col0);
#pragma unroll
                for (int k = 0; k < R; ++k) {
                    float h = (t == 0) ? hv[k].x : (t == 1) ? hv[k].y : (t == 2) ? hv[k].z : hv[k].w;
                    u64 hh = pack2(h);
                    fma2(accb[k*2+0], hh, w2p.x);
                    fma2(accb[k*2+1], hh, w2p.y);
                }
            }
        }

        // ---- +b2, LN, gelu; stacked; agg += w[f]*stacked ----
        {
            float wf = w_s[f];
#pragma unroll
            for (int k = 0; k < R; ++k) {
                float2 p0 = unpack2(accb[k*2+0]);
                float2 p1 = unpack2(accb[k*2+1]);
                float v0 = p0.x + vecs[384 + col0 + 0];
                float v1 = p0.y + vecs[384 + col0 + 1];
                float v2 = p1.x + vecs[384 + col0 + 2];
                float v3 = p1.y + vecs[384 + col0 + 3];
                float s1 = red32(v0 + v1 + v2 + v3);
                float s2 = red32(v0*v0 + v1*v1 + v2*v2 + v3*v3);
                float mu  = s1 * (1.0f / H2);
                float var = s2 * (1.0f / H2) - mu * mu;
                float inv = rsqrtf(var + LN_EPS);
                float2 r0 = unpack2(accr2[k*2+0]);
                float2 r1 = unpack2(accr2[k*2+1]);
                float hv0 = gelu_exact((v0 - mu) * inv * vecs[512 + col0 + 0] + vecs[640 + col0 + 0]);
                float hv1 = gelu_exact((v1 - mu) * inv * vecs[512 + col0 + 1] + vecs[640 + col0 + 1]);
                float hv2 = gelu_exact((v2 - mu) * inv * vecs[512 + col0 + 2] + vecs[640 + col0 + 2]);
                float hv3 = gelu_exact((v3 - mu) * inv * vecs[512 + col0 + 3] + vecs[640 + col0 + 3]);
                agg[k*4+0] = fmaf(wf, hv0 + 0.1f * (r0.x + vecs[768 + col0 + 0]), agg[k*4+0]);
                agg[k*4+1] = fmaf(wf, hv1 + 0.1f * (r0.y + vecs[768 + col0 + 1]), agg[k*4+1]);
                agg[k*4+2] = fmaf(wf, hv2 + 0.1f * (r1.x + vecs[768 + col0 + 2]), agg[k*4+2]);
                agg[k*4+3] = fmaf(wf, hv3 + 0.1f * (r1.y + vecs[768 + col0 + 3]), agg[k*4+3]);
            }
        }
    }

    // ---- head: per-row dots with Wpi/Wa/Wb, reduce over warp ----
    float ppi[12], paa[12], pbb[12];
#pragma unroll
    for (int q = 0; q < 12; ++q) { ppi[q] = 0.f; paa[q] = 0.f; pbb[q] = 0.f; }

#pragma unroll
    for (int j = 0; j < 4; ++j) {
        int r = col0 + j;
        float wp0 = __ldg(Wpi + r * 3 + 0), wp1 = __ldg(Wpi + r * 3 + 1), wp2 = __ldg(Wpi + r * 3 + 2);
        float wa0 = __ldg(Wa  + r * 3 + 0), wa1 = __ldg(Wa  + r * 3 + 1), wa2 = __ldg(Wa  + r * 3 + 2);
        float wb0 = __ldg(Wb  + r * 3 + 0), wb1 = __ldg(Wb  + r * 3 + 1), wb2 = __ldg(Wb  + r * 3 + 2);
        float bs = __ldg(bias + r);
#pragma unroll
        for (int k = 0; k < R; ++k) {
            float a = agg[k*4+j] + bs;
            ppi[k*3+0] = fmaf(a, wp0, ppi[k*3+0]);
            ppi[k*3+1] = fmaf(a, wp1, ppi[k*3+1]);
            ppi[k*3+2] = fmaf(a, wp2, ppi[k*3+2]);
            paa[k*3+0] = fmaf(a, wa0, paa[k*3+0]);
            paa[k*3+1] = fmaf(a, wa1, paa[k*3+1]);
            paa[k*3+2] = fmaf(a, wa2, paa[k*3+2]);
            pbb[k*3+0] = fmaf(a, wb0, pbb[k*3+0]);
            pbb[k*3+1] = fmaf(a, wb1, pbb[k*3+1]);
            pbb[k*3+2] = fmaf(a, wb2, pbb[k*3+2]);
        }
    }
#pragma unroll
    for (int q = 0; q < 12; ++q) {
        ppi[q] = red32(ppi[q]);
        paa[q] = red32(paa[q]);
        pbb[q] = red32(pbb[q]);
    }

    if (cg < R) {
        int k = cg;                 // lane k writes row rg+16k
        float l0 = ppi[k*3+0] + __ldg(bpi + 0);
        float l1 = ppi[k*3+1] + __ldg(bpi + 1);
        float l2 = ppi[k*3+2] + __ldg(bpi + 2);
        float m = fmaxf(l0, fmaxf(l1, l2));
        float e0 = expf(l0 - m), e1 = expf(l1 - m), e2 = expf(l2 - m);
        float inv_es = 1.0f / (e0 + e1 + e2);
        float pred = 0.0f;
#pragma unroll
        for (int q = 0; q < 3; ++q) {
            float ev = (q == 0) ? e0 : (q == 1) ? e1 : e2;
            float ak = clipf(softplus_f(paa[k*3+q] + __ldg(ba + q)) + 1.01f, 1.01f, 100.0f);
            float bk = clipf(softplus_f(pbb[k*3+q] + __ldg(bb + q)) + 1.01f, 1.01f, 100.0f);
            pred += (ev * inv_es) * (ak / (ak + bk));
        }
        out[base_row + rg + 16 * k] = clipf(pred, 0.001f, 0.999f);
    }
}

extern "C" void kernel_launch(void* const* d_in, const int* in_sizes, int n_in,
                              void* d_out, int out_size) {
    (void)in_sizes; (void)n_in; (void)out_size;
    cudaFuncSetAttribute(nam_kernel,
                         cudaFuncAttributeMaxDynamicSharedMemorySize, SMEM_BYTES);
    const float* x       = (const float*)d_in[0];
    const float* centers = (const float*)d_in[1];
    const float* logw    = (const float*)d_in[2];
    const float* W1      = (const float*)d_in[3];
    const float* b1      = (const float*)d_in[4];
    const float* g1      = (const float*)d_in[5];
    const float* be1     = (const float*)d_in[6];
    const float* W2      = (const float*)d_in[7];
    const float* b2      = (const float*)d_in[8];
    const float* g2      = (const float*)d_in[9];
    const float* be2     = (const float*)d_in[10];
    const float* Wr      = (const float*)d_in[11];
    const float* br      = (const float*)d_in[12];
    const float* att     = (const float*)d_in[13];
    const float* bias    = (const float*)d_in[14];
    const float* Wpi     = (const float*)d_in[15];
    const float* bpi     = (const float*)d_in[16];
    const float* Wa      = (const float*)d_in[17];
    const float* ba      = (const float*)d_in[18];
    const float* Wb      = (const float*)d_in[19];
    const float* bb      = (const float*)d_in[20];
    float* out = (float*)d_out;

    nam_kernel<<<B_TOT / TM, NTHR, SMEM_BYTES>>>(
        x, centers, logw, W1, b1, g1, be1, W2, b2, g2, be2, Wr, br,
        att, bias, Wpi, bpi, Wa, ba, Wb, bb, out);
}